// round 3
// baseline (speedup 1.0000x reference)
#include <cuda_runtime.h>
#include <cuda_bf16.h>

// Shapes fixed by setup_inputs: bs=16, nq=900, nc=91, T=1600  ->  N=14400
#define NC     91
#define NMAX   14400
#define NTILE  16
#define TTILE  160          // threads per block
#define TPB    (2*TTILE)    // targets per block (2 adjacent per thread)

typedef unsigned long long ull;

// Scratch: class-cost table cc2[n][c] = 2*(pos-neg) + 2   (5.24 MB)
__device__ float g_cc[NMAX * NC];

// ---- packed f32x2 helpers (sm_100+) ---------------------------------------
__device__ __forceinline__ ull f2pk(float a, float b) {
    ull r; asm("mov.b64 %0, {%1, %2};" : "=l"(r) : "f"(a), "f"(b)); return r;
}
__device__ __forceinline__ void f2un(float& a, float& b, ull v) {
    asm("mov.b64 {%0, %1}, %2;" : "=f"(a), "=f"(b) : "l"(v));
}
__device__ __forceinline__ ull f2add(ull a, ull b) {
    ull r; asm("add.rn.f32x2 %0, %1, %2;" : "=l"(r) : "l"(a), "l"(b)); return r;
}
__device__ __forceinline__ ull f2mul(ull a, ull b) {
    ull r; asm("mul.rn.f32x2 %0, %1, %2;" : "=l"(r) : "l"(a), "l"(b)); return r;
}
__device__ __forceinline__ ull f2fma(ull a, ull b, ull c) {
    ull r; asm("fma.rn.f32x2 %0, %1, %2, %3;" : "=l"(r) : "l"(a), "l"(b), "l"(c)); return r;
}
__device__ __forceinline__ ull fdup(float v) {            // (v, v) as b64
    unsigned u = __float_as_uint(v);
    return (ull)u | ((ull)u << 32);
}

// ---------------------------------------------------------------------------
// Kernel 1: per-(query, class) focal classification cost, float4-vectorized.
//   p = sigmoid(x);  s = 1+e^x, r = 1/s = 1-p, ls = log s = -log(1-p)
//   pos = 0.25*r*r*(ls - x);  neg = 0.75*p*p*ls
//   stored: cc2 = 2*(pos-neg) + 2   (folds COST_CLASS=2 and giou's +1)
// ---------------------------------------------------------------------------
__device__ __forceinline__ float focal_cc(float x)
{
    float ex = __expf(x);
    float s  = 1.0f + ex;
    float r  = __frcp_rn(s);     // 1 - p
    float ls = __logf(s);        // -log(1-p)
    float p  = 1.0f - r;
    float pos = 0.25f * r * r * (ls - x);
    float neg = 0.75f * p * p * ls;
    return 2.0f * (pos - neg) + 2.0f;
}

__global__ void class_cost_kernel(const float4* __restrict__ logits4, int total4)
{
    int i = blockIdx.x * blockDim.x + threadIdx.x;
    if (i >= total4) return;
    float4 x = logits4[i];
    float4 o;
    o.x = focal_cc(x.x);
    o.y = focal_cc(x.y);
    o.z = focal_cc(x.z);
    o.w = focal_cc(x.w);
    ((float4*)g_cc)[i] = o;
}

// ---------------------------------------------------------------------------
// Kernel 2: N x T cost matrix. Thread owns targets (t0, t0+1) packed into the
// two lanes of f32x2 registers; iterates 16 queries staged in shared memory.
// Query scalars that feed packed ops are stored PRE-DUPLICATED in smem so an
// LDS.128 delivers two broadcast-packed b64 operands with zero pack MOVs.
// ---------------------------------------------------------------------------
__global__ __launch_bounds__(TTILE)
void cost_matrix_kernel(const float* __restrict__ pred_boxes,  // [N,4] cxcywh
                        const int*   __restrict__ tgt_ids,     // [T]
                        const float* __restrict__ tgt_bbox,    // [T,4] cxcywh
                        float*       __restrict__ out,         // [N,T]
                        int N, int T)
{
    __shared__ float  s_cc[NTILE * NC];
    __shared__ float4 s_xyxy[NTILE];          // query xyxy (scalar min/max use)
    __shared__ ull    s_dup[NTILE][6];        // {cx2, cy2, w2, h2, a2, pad}

    const int n0 = blockIdx.y * NTILE;
    const int t0 = blockIdx.x * TPB + 2 * threadIdx.x;

    for (int i = threadIdx.x; i < NTILE * NC; i += TTILE)
        s_cc[i] = g_cc[n0 * NC + i];

    if (threadIdx.x < NTILE) {
        int n = n0 + threadIdx.x;
        float4 b = __ldg(((const float4*)pred_boxes) + n);
        float hw = 0.5f * b.z, hh = 0.5f * b.w;
        s_xyxy[threadIdx.x] = make_float4(b.x - hw, b.y - hh, b.x + hw, b.y + hh);
        s_dup[threadIdx.x][0] = fdup(b.x);
        s_dup[threadIdx.x][1] = fdup(b.y);
        s_dup[threadIdx.x][2] = fdup(b.z);
        s_dup[threadIdx.x][3] = fdup(b.w);
        s_dup[threadIdx.x][4] = fdup(b.z * b.w);
    }
    __syncthreads();

    // ---- per-thread target constants (lane0 = A = t0, lane1 = B = t0+1) ----
    float4 ba = __ldg(((const float4*)tgt_bbox) + t0);
    float4 bb = __ldg(((const float4*)tgt_bbox) + t0 + 1);
    const int clsA = tgt_ids[t0];
    const int clsB = tgt_ids[t0 + 1];

    const ull ntcx2 = f2pk(-ba.x, -bb.x);     // negated -> diff via add
    const ull ntcy2 = f2pk(-ba.y, -bb.y);
    const ull ntw2  = f2pk(-ba.z, -bb.z);
    const ull nth2  = f2pk(-ba.w, -bb.w);
    const ull ta2   = f2pk(ba.z * ba.w, bb.z * bb.w);
    const ull nOne2 = fdup(-1.0f);

    const float ahw = 0.5f * ba.z, ahh = 0.5f * ba.w;
    const float bhw = 0.5f * bb.z, bhh = 0.5f * bb.w;
    const float tx0A = ba.x - ahw, ty0A = ba.y - ahh, tx1A = ba.x + ahw, ty1A = ba.y + ahh;
    const float tx0B = bb.x - bhw, ty0B = bb.y - bhh, tx1B = bb.x + bhw, ty1B = bb.y + bhh;

    float* op = out + (size_t)n0 * T + t0;

    #pragma unroll
    for (int i = 0; i < NTILE; i++) {
        const float4 q = s_xyxy[i];                                    // LDS.128 bcast
        const ulonglong2 p0 = *(const ulonglong2*)&s_dup[i][0];        // cx2, cy2
        const ulonglong2 p1 = *(const ulonglong2*)&s_dup[i][2];        // w2, h2
        const ull a2 = s_dup[i][4];                                    // area2
        const float ccA = s_cc[i * NC + clsA];
        const float ccB = s_cc[i * NC + clsB];

        // ---- L1 (packed diffs, scalar abs-sum with |.| input modifiers) ----
        ull d1 = f2add(p0.x, ntcx2);
        ull d2 = f2add(p0.y, ntcy2);
        ull d3 = f2add(p1.x, ntw2);
        ull d4 = f2add(p1.y, nth2);
        float d1A,d1B,d2A,d2B,d3A,d3B,d4A,d4B;
        f2un(d1A,d1B,d1); f2un(d2A,d2B,d2); f2un(d3A,d3B,d3); f2un(d4A,d4B,d4);
        float lA = (fabsf(d1A)+fabsf(d2A)) + (fabsf(d3A)+fabsf(d4A));
        float lB = (fabsf(d1B)+fabsf(d2B)) + (fabsf(d3B)+fabsf(d4B));

        // ---- scalar min/max (no packed FMNMX on sm_103a) ----
        float ix0A = fmaxf(q.x, tx0A), iy0A = fmaxf(q.y, ty0A);
        float ix1A = fminf(q.z, tx1A), iy1A = fminf(q.w, ty1A);
        float ex0A = fminf(q.x, tx0A), ey0A = fminf(q.y, ty0A);
        float ex1A = fmaxf(q.z, tx1A), ey1A = fmaxf(q.w, ty1A);
        float ix0B = fmaxf(q.x, tx0B), iy0B = fmaxf(q.y, ty0B);
        float ix1B = fminf(q.z, tx1B), iy1B = fminf(q.w, ty1B);
        float ex0B = fminf(q.x, tx0B), ey0B = fminf(q.y, ty0B);
        float ex1B = fmaxf(q.z, tx1B), ey1B = fmaxf(q.w, ty1B);

        // intersection (scalar clamp+mul, then repack once)
        float interA = fmaxf(ix1A - ix0A, 0.0f) * fmaxf(iy1A - iy0A, 0.0f);
        float interB = fmaxf(ix1B - ix0B, 0.0f) * fmaxf(iy1B - iy0B, 0.0f);
        ull inter2 = f2pk(interA, interB);

        // packed union / enclosing / numerator / denominator
        ull sum2 = f2add(a2, ta2);
        ull uni2 = f2fma(inter2, nOne2, sum2);                 // sum - inter
        ull ew2  = f2fma(f2pk(ex0A, ex0B), nOne2, f2pk(ex1A, ex1B));
        ull eh2  = f2fma(f2pk(ey0A, ey0B), nOne2, f2pk(ey1A, ey1B));
        ull ae2  = f2mul(ew2, eh2);
        ull num2 = f2fma(uni2, uni2, f2mul(inter2, ae2));      // uni^2 + inter*ae
        ull den2 = f2mul(uni2, ae2);

        float numA,numB,denA,denB;
        f2un(numA,numB,num2); f2un(denA,denB,den2);

        // term = iou + uni/ae = num/den  (single approx division per lane)
        float cA = fmaf(-2.0f, __fdividef(numA, denA), fmaf(5.0f, lA, ccA));
        float cB = fmaf(-2.0f, __fdividef(numB, denB), fmaf(5.0f, lB, ccB));

        *(float2*)(op + (size_t)i * T) = make_float2(cA, cB);
    }
}

extern "C" void kernel_launch(void* const* d_in, const int* in_sizes, int n_in,
                              void* d_out, int out_size)
{
    const float* pred_logits = (const float*)d_in[0];   // [bs, nq, nc]
    const float* pred_boxes  = (const float*)d_in[1];   // [bs, nq, 4]
    const int*   tgt_ids     = (const int*)  d_in[2];   // [T]
    const float* tgt_bbox    = (const float*)d_in[3];   // [T, 4]
    float*       out         = (float*)d_out;           // [N, T]

    const int N = in_sizes[1] / 4;       // 14400
    const int T = in_sizes[2];           // 1600

    // Kernel 1: class cost table (N*91 = 1,310,400, divisible by 4)
    {
        int total4 = (N * NC) / 4;
        int threads = 256;
        class_cost_kernel<<<(total4 + threads - 1) / threads, threads>>>(
            (const float4*)pred_logits, total4);
    }

    // Kernel 2: main cost matrix
    {
        dim3 grid(T / TPB, (N + NTILE - 1) / NTILE);   // 5 x 900
        cost_matrix_kernel<<<grid, TTILE>>>(pred_boxes, tgt_ids, tgt_bbox, out, N, T);
    }
}